// round 6
// baseline (speedup 1.0000x reference)
#include <cuda_runtime.h>

#define BB 256
#define TT 1024
#define HH 64
#define GG 256   // 4*H gates

#define L0_CTAS 16
#define L0_ROWS 16
#define LN_CTAS 32
#define LN_ROWS 8
#define NLAYERS 5
#define GRID_WF (L0_CTAS + 4 * LN_CTAS)   // 144 <= 148 SMs -> all co-resident
#define WSZ (GG * HH)

// Per-layer hidden-state buffers (5 x 64 MB) + progress flags. No allocs.
__device__ float g_h[NLAYERS][BB * TT * HH];
__device__ int   g_flags[NLAYERS][LN_CTAS];

typedef unsigned long long ull;

__device__ __forceinline__ float sigf(float x) {
    x = fminf(fmaxf(x, -30.f), 30.f);
    float e = __expf(-x);
    return __fdividef(1.0f, 1.0f + e);
}
__device__ __forceinline__ float tanhf_fast(float x) {
    x = fminf(fmaxf(x, -15.f), 15.f);
    float e = __expf(-2.0f * x);
    return __fdividef(1.0f - e, 1.0f + e);
}

// Blackwell packed fp32 ops (PTX-only).
#define FFMA2(acc, a, b) \
    asm("fma.rn.f32x2 %0, %1, %2, %0;" : "+l"(acc) : "l"(a), "l"(b))
#define ADD2(d, a, b) \
    asm("add.rn.f32x2 %0, %1, %2;" : "=l"(d) : "l"(a), "l"(b))
#define UNPACK2(lo, hi, p) \
    asm("mov.b64 {%0,%1}, %2;" : "=f"(lo), "=f"(hi) : "l"(p))
#define PACK2(p, lo, hi) \
    asm("mov.b64 %0, {%1,%2};" : "=l"(p) : "f"(lo), "f"(hi))

__device__ __forceinline__ int ld_acquire(const int* p) {
    int v;
    asm volatile("ld.global.acquire.gpu.b32 %0, [%1];" : "=r"(v) : "l"(p) : "memory");
    return v;
}
__device__ __forceinline__ void st_release(int* p, int v) {
    asm volatile("st.global.release.gpu.b32 [%0], %1;" :: "l"(p), "r"(v) : "memory");
}

__global__ void reset_flags() {
    int i = threadIdx.x;
    if (i < NLAYERS * LN_CTAS) ((int*)g_flags)[i] = 0;
}

// ---------------------------------------------------------------------------
// Wavefront kernel: all 5 LSTM layers concurrently, skewed in time.
//   bid <  16             : layer 0, 16 batch rows   (x is scalar/step)
//   bid >= 16             : layer 1+ (li = (bid-16)/32), 8 batch rows
// Thread g owns gate row g: W_hh row (+ W_ih row for l>=1) in registers.
// h handoff: global g_h[l] + monotonic flags (release/acquire), consumer lags
// ~4 steps so h_prev loads are latency-hidden.
// ---------------------------------------------------------------------------
__global__ void __launch_bounds__(256, 1)
wavefront(const float* __restrict__ x,     // [B,T]
          const float* __restrict__ wih0,  // [256]
          const float* __restrict__ wihR,  // [4,256,64]
          const float* __restrict__ whh,   // [5,256,64]
          const float* __restrict__ bih,   // [5,256]
          const float* __restrict__ bhh)   // [5,256]
{
    __shared__ __align__(16) float hs[L0_ROWS][64];      // own h state
    __shared__ float gsm[L0_ROWS][GG];                   // gate values
    __shared__ __align__(16) float xr[4][LN_ROWS][64];   // h_prev ring (l>=1)
    __shared__ float xs0[4][L0_ROWS];                    // x ring (layer 0)

    const int tid = threadIdx.x;
    const int bid = blockIdx.x;

    if (bid < L0_CTAS) {
        // ============================ layer 0 ============================
        const int r0 = bid * L0_ROWS;
        ull whh2[32];
        {
            const ull* wr = reinterpret_cast<const ull*>(whh + tid * 64);
            #pragma unroll
            for (int k = 0; k < 32; k++) whh2[k] = wr[k];
        }
        const float wsc  = wih0[tid];
        const float bsum = bih[tid] + bhh[tid];

        #pragma unroll
        for (int i = 0; i < 4; i++) {
            int v = tid + 256 * i;
            hs[v >> 6][v & 63] = 0.f;
        }
        float c0 = 0.f, c1 = 0.f, c2 = 0.f, c3 = 0.f;

        float q = 0.f;
        if (tid < L0_ROWS) {
            const float* xp = x + (size_t)(r0 + tid) * TT;
            xs0[0][tid] = xp[0];
            xs0[1][tid] = xp[1];
            q = xp[2];
        }
        __syncthreads();

        int* myflag = &g_flags[0][bid];
        for (int t = 0; t < TT; ++t) {
            // ---- phase A: gates for 16 rows ----
            #pragma unroll
            for (int r = 0; r < L0_ROWS; ++r) {
                const ulonglong2* hp = reinterpret_cast<const ulonglong2*>(hs[r]);
                ull a0 = 0, a1 = 0, a2 = 0, a3 = 0;
                #pragma unroll
                for (int k = 0; k < 8; k++) {
                    ulonglong2 v1 = hp[2 * k];
                    ulonglong2 v2 = hp[2 * k + 1];
                    FFMA2(a0, whh2[4 * k],     v1.x);
                    FFMA2(a1, whh2[4 * k + 1], v1.y);
                    FFMA2(a2, whh2[4 * k + 2], v2.x);
                    FFMA2(a3, whh2[4 * k + 3], v2.y);
                }
                ull u, v; ADD2(u, a0, a1); ADD2(v, a2, a3); ADD2(u, u, v);
                float lo, hi; UNPACK2(lo, hi, u);
                float a = lo + hi + bsum + wsc * xs0[t & 3][r];
                float val = (tid >= 128 && tid < 192) ? tanhf_fast(a) : sigf(a);
                gsm[r][tid] = val;
            }
            __syncthreads();
            // ---- phase B: state update (4 values/thread) ----
            #pragma unroll
            for (int i = 0; i < 4; i++) {
                int v = tid + 256 * i;
                int r = v >> 6, j = v & 63;
                float iv = gsm[r][j];
                float fv = gsm[r][64 + j];
                float gv = gsm[r][128 + j];
                float ov = gsm[r][192 + j];
                float c = (i == 0) ? c0 : (i == 1) ? c1 : (i == 2) ? c2 : c3;
                c = fv * c + iv * gv;
                if (i == 0) c0 = c; else if (i == 1) c1 = c;
                else if (i == 2) c2 = c; else c3 = c;
                float hval = ov * tanhf_fast(c);
                hs[r][j] = hval;
                g_h[0][((size_t)(r0 + r) * TT + t) * 64 + j] = hval;
            }
            if (tid < L0_ROWS) {
                if (t + 2 < TT) xs0[(t + 2) & 3][tid] = q;
                if (t + 3 < TT) q = x[(size_t)(r0 + tid) * TT + (t + 3)];
            }
            bool publish = ((t & 1) == 1) || (t == TT - 1);
            if (publish) __threadfence();
            __syncthreads();
            if (publish && tid == 0) st_release(myflag, t + 1);
        }
    } else {
        // ============================ layers 1..4 ============================
        const int li    = (bid - L0_CTAS) >> 5;   // 0..3
        const int l     = li + 1;
        const int chunk = (bid - L0_CTAS) & 31;
        const int r0    = chunk * LN_ROWS;

        ull whh2[32], wih2[32];
        {
            const ull* wr = reinterpret_cast<const ull*>(whh + l * WSZ + tid * 64);
            #pragma unroll
            for (int k = 0; k < 32; k++) whh2[k] = wr[k];
            const ull* wi = reinterpret_cast<const ull*>(wihR + li * WSZ + tid * 64);
            #pragma unroll
            for (int k = 0; k < 32; k++) wih2[k] = wi[k];
        }
        const float bsum = bih[l * GG + tid] + bhh[l * GG + tid];

        #pragma unroll
        for (int i = 0; i < 2; i++) {
            int v = tid + 256 * i;
            hs[v >> 6][v & 63] = 0.f;
        }
        float c0 = 0.f, c1 = 0.f;

        const int* prod = &g_flags[l - 1][(l == 1) ? (chunk >> 1) : chunk];
        int* myflag = &g_flags[l][chunk];
        const float* hprev = g_h[l - 1];

        // per-thread staging coordinates (2 values/thread)
        const int rA = tid >> 6,        jA = tid & 63;        // value tid
        const int rB = 4 + (tid >> 6),  jB = tid & 63;        // value tid+256
        const size_t baseA = (size_t)(r0 + rA) * TT * 64 + jA;
        const size_t baseB = (size_t)(r0 + rB) * TT * 64 + jB;

        // prologue: stage h_prev[0..1], prefetch h_prev[2]
        while (ld_acquire(prod) < 2) __nanosleep(128);
        #pragma unroll
        for (int s = 0; s < 2; s++) {
            xr[s][rA][jA] = __ldcg(hprev + baseA + (size_t)s * 64);
            xr[s][rB][jB] = __ldcg(hprev + baseB + (size_t)s * 64);
        }
        while (ld_acquire(prod) < 3) __nanosleep(128);
        float qA = __ldcg(hprev + baseA + 2 * 64);
        float qB = __ldcg(hprev + baseB + 2 * 64);
        __syncthreads();

        for (int t = 0; t < TT; ++t) {
            // early flag sample (consumed in phase B; hides acquire latency)
            int fl = (t + 3 < TT) ? ld_acquire(prod) : 0x7fffffff;

            // ---- phase A: gates for 8 rows (h-part + x-part) ----
            #pragma unroll
            for (int r = 0; r < LN_ROWS; ++r) {
                const ulonglong2* hp = reinterpret_cast<const ulonglong2*>(hs[r]);
                const ulonglong2* xp = reinterpret_cast<const ulonglong2*>(xr[t & 3][r]);
                ull a0 = 0, a1 = 0, a2 = 0, a3 = 0;
                #pragma unroll
                for (int k = 0; k < 8; k++) {
                    ulonglong2 v1 = hp[2 * k];
                    ulonglong2 v2 = hp[2 * k + 1];
                    ulonglong2 w1 = xp[2 * k];
                    ulonglong2 w2 = xp[2 * k + 1];
                    FFMA2(a0, whh2[4 * k],     v1.x);
                    FFMA2(a1, whh2[4 * k + 1], v1.y);
                    FFMA2(a2, whh2[4 * k + 2], v2.x);
                    FFMA2(a3, whh2[4 * k + 3], v2.y);
                    FFMA2(a0, wih2[4 * k],     w1.x);
                    FFMA2(a1, wih2[4 * k + 1], w1.y);
                    FFMA2(a2, wih2[4 * k + 2], w2.x);
                    FFMA2(a3, wih2[4 * k + 3], w2.y);
                }
                ull u, v; ADD2(u, a0, a1); ADD2(v, a2, a3); ADD2(u, u, v);
                float lo, hi; UNPACK2(lo, hi, u);
                float a = lo + hi + bsum;
                float val = (tid >= 128 && tid < 192) ? tanhf_fast(a) : sigf(a);
                gsm[r][tid] = val;
            }
            __syncthreads();
            // ---- phase B: update (2 values/thread) + h_prev pipeline ----
            {
                float iv = gsm[rA][jA];
                float fv = gsm[rA][64 + jA];
                float gv = gsm[rA][128 + jA];
                float ov = gsm[rA][192 + jA];
                c0 = fv * c0 + iv * gv;
                float hval = ov * tanhf_fast(c0);
                hs[rA][jA] = hval;
                g_h[l][baseA + (size_t)t * 64] = hval;
            }
            {
                float iv = gsm[rB][jB];
                float fv = gsm[rB][64 + jB];
                float gv = gsm[rB][128 + jB];
                float ov = gsm[rB][192 + jB];
                c1 = fv * c1 + iv * gv;
                float hval = ov * tanhf_fast(c1);
                hs[rB][jB] = hval;
                g_h[l][baseB + (size_t)t * 64] = hval;
            }
            if (t + 2 < TT) {
                xr[(t + 2) & 3][rA][jA] = qA;
                xr[(t + 2) & 3][rB][jB] = qB;
            }
            if (t + 3 < TT) {
                int tgt = (t + 4 < TT) ? (t + 4) : TT;
                while (fl < tgt) { __nanosleep(128); fl = ld_acquire(prod); }
                qA = __ldcg(hprev + baseA + (size_t)(t + 3) * 64);
                qB = __ldcg(hprev + baseB + (size_t)(t + 3) * 64);
            }
            bool publish = (((t & 1) == 1) || (t == TT - 1)) && (l < 4);
            if (publish) __threadfence();
            __syncthreads();
            if (publish && tid == 0) st_release(myflag, t + 1);
        }
    }
}

// ---------------------------------------------------------------------------
// Head: out = relu(relu(h) @ W1^T + b1) @ W2^T + b2 (packed FFMA2).
// ---------------------------------------------------------------------------
__global__ void __launch_bounds__(256)
fc_kernel(const float* __restrict__ hin,  // [B,T,64]
          const float* __restrict__ W1,   // [64,64]
          const float* __restrict__ b1,   // [64]
          const float* __restrict__ W2,   // [1,64]
          const float* __restrict__ b2,   // [1]
          float* __restrict__ out)        // [B*T]
{
    __shared__ ull  W1P[64 * 32];
    __shared__ float b1s[64];
    __shared__ float w2s[64];
    __shared__ float hsm[8][2][64];

    for (int i = threadIdx.x; i < 64 * 32; i += 256) {
        int k = i >> 5, l = i & 31;
        ull p; PACK2(p, W1[l * 64 + k], W1[(l + 32) * 64 + k]);
        W1P[k * 32 + l] = p;
    }
    if (threadIdx.x < 64) {
        b1s[threadIdx.x] = b1[threadIdx.x];
        w2s[threadIdx.x] = W2[threadIdx.x];
    }
    __syncthreads();
    const float b2v = b2[0];

    const int warp = threadIdx.x >> 5, lane = threadIdx.x & 31;
    ull ybias; PACK2(ybias, b1s[lane], b1s[lane + 32]);
    const float w2lo = w2s[lane], w2hi = w2s[lane + 32];

    const int npairs = BB * TT / 2;
    for (int pair = blockIdx.x * 8 + warp; pair < npairs; pair += gridDim.x * 8) {
        size_t p0 = (size_t)pair * 2;
        float h00 = fmaxf(hin[p0 * 64 + lane], 0.f);
        float h01 = fmaxf(hin[p0 * 64 + 32 + lane], 0.f);
        float h10 = fmaxf(hin[(p0 + 1) * 64 + lane], 0.f);
        float h11 = fmaxf(hin[(p0 + 1) * 64 + 32 + lane], 0.f);
        hsm[warp][0][lane]      = h00;
        hsm[warp][0][lane + 32] = h01;
        hsm[warp][1][lane]      = h10;
        hsm[warp][1][lane + 32] = h11;
        __syncwarp();

        ull y0a = ybias, y0b = 0, y1a = ybias, y1b = 0;
        #pragma unroll
        for (int k = 0; k < 64; k += 2) {
            ull w0 = W1P[k * 32 + lane];
            ull w1 = W1P[(k + 1) * 32 + lane];
            float hv00 = hsm[warp][0][k], hv01 = hsm[warp][0][k + 1];
            float hv10 = hsm[warp][1][k], hv11 = hsm[warp][1][k + 1];
            ull d00; PACK2(d00, hv00, hv00);
            ull d01; PACK2(d01, hv01, hv01);
            ull d10; PACK2(d10, hv10, hv10);
            ull d11; PACK2(d11, hv11, hv11);
            FFMA2(y0a, w0, d00);
            FFMA2(y0b, w1, d01);
            FFMA2(y1a, w0, d10);
            FFMA2(y1b, w1, d11);
        }
        ADD2(y0a, y0a, y0b);
        ADD2(y1a, y1a, y1b);
        float u0, u1, v0, v1;
        UNPACK2(u0, u1, y0a);
        UNPACK2(v0, v1, y1a);
        float part0 = fmaxf(u0, 0.f) * w2lo + fmaxf(u1, 0.f) * w2hi;
        float part1 = fmaxf(v0, 0.f) * w2lo + fmaxf(v1, 0.f) * w2hi;
        ull pp; PACK2(pp, part0, part1);
        #pragma unroll
        for (int off = 16; off; off >>= 1) {
            ull o = __shfl_down_sync(0xffffffffu, pp, off);
            ADD2(pp, pp, o);
        }
        if (lane == 0) {
            UNPACK2(part0, part1, pp);
            reinterpret_cast<float2*>(out)[pair] =
                make_float2(part0 + b2v, part1 + b2v);
        }
        __syncwarp();
    }
}

extern "C" void kernel_launch(void* const* d_in, const int* in_sizes, int n_in,
                              void* d_out, int out_size)
{
    const float* x    = (const float*)d_in[0];  // [256,1024,1]
    const float* wih0 = (const float*)d_in[1];  // [256,1]
    const float* wihR = (const float*)d_in[2];  // [4,256,64]
    const float* whh  = (const float*)d_in[3];  // [5,256,64]
    const float* bih  = (const float*)d_in[4];  // [5,256]
    const float* bhh  = (const float*)d_in[5];  // [5,256]
    const float* W1   = (const float*)d_in[6];  // [64,64]
    const float* b1   = (const float*)d_in[7];  // [64]
    const float* W2   = (const float*)d_in[8];  // [1,64]
    const float* b2   = (const float*)d_in[9];  // [1]
    float* out = (float*)d_out;                 // [256,1024,1]
    (void)in_sizes; (void)n_in; (void)out_size; // future == 0 per setup

    void* pH = nullptr;
    cudaGetSymbolAddress(&pH, g_h);
    float* h4 = (float*)pH + 4 * (size_t)BB * TT * HH;

    reset_flags<<<1, 256>>>();
    wavefront<<<GRID_WF, 256>>>(x, wih0, wihR, whh, bih, bhh);
    fc_kernel<<<2048, 256>>>(h4, W1, b1, W2, b2, out);
}

// round 7
// speedup vs baseline: 1.5004x; 1.5004x over previous
#include <cuda_runtime.h>
#include <cuda_fp16.h>

#define BB 256
#define TT 1024
#define HH 64
#define GG 256
#define NL 5
#define CPL 16
#define RPC 16
#define AST 72   // smem half-stride: rA*36+word ≡ distinct banks

__device__ float g_h[NL][(size_t)BB * TT * HH];
__device__ int   g_flags[NL][CPL];

__device__ __forceinline__ float sigf(float x) {
    x = fminf(fmaxf(x, -30.f), 30.f);
    return __fdividef(1.0f, 1.0f + __expf(-x));
}
__device__ __forceinline__ float tanhf_fast(float x) {
    x = fminf(fmaxf(x, -15.f), 15.f);
    float e = __expf(-2.0f * x);
    return __fdividef(1.0f - e, 1.0f + e);
}
__device__ __forceinline__ int ld_acquire(const int* p) {
    int v;
    asm volatile("ld.global.acquire.gpu.b32 %0, [%1];" : "=r"(v) : "l"(p) : "memory");
    return v;
}
__device__ __forceinline__ void st_release(int* p, int v) {
    asm volatile("st.global.release.gpu.b32 [%0], %1;" :: "l"(p), "r"(v) : "memory");
}
__global__ void reset_flags() {
    int i = threadIdx.x;
    if (i < NL * CPL) ((int*)g_flags)[i] = 0;
}

#define MMA(d0, d1, d2, d3, a0, a1, a2, a3, b0, b1)                        \
    asm volatile(                                                          \
        "mma.sync.aligned.m16n8k16.row.col.f32.f16.f16.f32 "               \
        "{%0,%1,%2,%3}, {%4,%5,%6,%7}, {%8,%9}, {%0,%1,%2,%3};"            \
        : "+f"(d0), "+f"(d1), "+f"(d2), "+f"(d3)                           \
        : "r"(a0), "r"(a1), "r"(a2), "r"(a3), "r"(b0), "r"(b1))

__device__ __forceinline__ void split2(float x, __half& hi, __half& lo) {
    hi = __float2half_rn(x);
    lo = __float2half_rn(x - __half2float(hi));
}
__device__ __forceinline__ unsigned packh(__half a, __half b) {
    __half2 h = __halves2half2(a, b);
    return *reinterpret_cast<unsigned*>(&h);
}
__device__ __forceinline__ void sts_pair(__half* dh, __half* dl, float2 v) {
    __half h0, l0, h1, l1;
    split2(v.x, h0, l0); split2(v.y, h1, l1);
    *reinterpret_cast<unsigned*>(dh) = packh(h0, h1);
    *reinterpret_cast<unsigned*>(dl) = packh(l0, l1);
}

// ---------------------------------------------------------------------------
// Tensor-core wavefront: 80 CTAs = 5 layers x 16 chunks x 16 batch rows.
// Per step: gates D[16x256] = [h_own|h_prev][16x128] @ W[128x256] via
// compensated fp16 HMMA; cell update in registers; 1 barrier/step.
// ---------------------------------------------------------------------------
__global__ void __launch_bounds__(256, 1)
wavefront(const float* __restrict__ x,     // [B,T]
          const float* __restrict__ wih0,  // [256]
          const float* __restrict__ wihR,  // [4,256,64]
          const float* __restrict__ whh,   // [5,256,64]
          const float* __restrict__ bih,   // [5,256]
          const float* __restrict__ bhh)   // [5,256]
{
    __shared__ __half Hh[2][RPC][AST], Hl[2][RPC][AST];
    __shared__ __half Xh[4][RPC][AST], Xl[4][RPC][AST];
    __shared__ float xs0[4][RPC];

    const int tid = threadIdx.x;
    const int w   = tid >> 5, ln = tid & 31;
    const int li  = blockIdx.x / CPL, ch = blockIdx.x % CPL;
    const int r0  = ch * RPC;
    const bool L0 = (li == 0);
    const int rA = ln >> 2;          // fragment row 0..7
    const int cc = (ln & 3) * 2;     // fragment col pair
    const int u0 = 8 * w + cc;       // unit pair owned by this lane
    const int NKT = L0 ? 4 : 8;      // k-tiles (L0: no h_prev matmul)

    // ---- weight B-fragments (hi/lo) ----
    unsigned bhi[4][8][2], blo[4][8][2];
    #pragma unroll
    for (int gi = 0; gi < 4; gi++) {
        const int grow = gi * 64 + 8 * w + rA;
        #pragma unroll
        for (int kt = 0; kt < 8; kt++)
            #pragma unroll
            for (int hf = 0; hf < 2; hf++) {
                bhi[gi][kt][hf] = 0; blo[gi][kt][hf] = 0;
                if (kt < NKT) {
                    int kg = ((kt < 4) ? kt * 16 : (kt - 4) * 16) + cc + hf * 8;
                    const float* src = (kt < 4)
                        ? whh  + ((size_t)li * GG + grow) * HH + kg
                        : wihR + ((size_t)(li - 1) * GG + grow) * HH + kg;
                    float2 wv = *reinterpret_cast<const float2*>(src);
                    __half h0, l0, h1, l1;
                    split2(wv.x, h0, l0); split2(wv.y, h1, l1);
                    bhi[gi][kt][hf] = packh(h0, h1);
                    blo[gi][kt][hf] = packh(l0, l1);
                }
            }
    }
    float bs[4][2], ws[4][2];
    #pragma unroll
    for (int gi = 0; gi < 4; gi++)
        #pragma unroll
        for (int e = 0; e < 2; e++) {
            int gu = gi * 64 + u0 + e;
            bs[gi][e] = bih[li * GG + gu] + bhh[li * GG + gu];
            ws[gi][e] = L0 ? wih0[gu] : 0.f;
        }

    for (int i = tid; i < RPC * AST; i += 256) {
        (&Hh[0][0][0])[i] = __float2half(0.f);
        (&Hl[0][0][0])[i] = __float2half(0.f);
    }

    // stager: thread covers rows (srow, srow+8), unit pair su
    const int srow = tid >> 5;
    const int su   = 2 * ln;
    const size_t pb0 = ((size_t)(r0 + srow) * TT) * 64 + su;
    const size_t pb1 = ((size_t)(r0 + srow + 8) * TT) * 64 + su;
    const int* pf = li ? &g_flags[li - 1][ch] : nullptr;
    int* myf = &g_flags[li][ch];
    const float* hp = li ? g_h[li - 1] : nullptr;
    float* ho = g_h[li];
    float2 q0 = make_float2(0.f, 0.f), q1 = make_float2(0.f, 0.f);
    float qx = 0.f;

    if (!L0) {
        while (ld_acquire(pf) < 2) __nanosleep(64);
        #pragma unroll
        for (int s = 0; s < 2; s++) {
            sts_pair(&Xh[s][srow][su],     &Xl[s][srow][su],
                     *(const float2*)(hp + pb0 + (size_t)s * 64));
            sts_pair(&Xh[s][srow + 8][su], &Xl[s][srow + 8][su],
                     *(const float2*)(hp + pb1 + (size_t)s * 64));
        }
        while (ld_acquire(pf) < 3) __nanosleep(64);
        q0 = *(const float2*)(hp + pb0 + 2 * 64);
        q1 = *(const float2*)(hp + pb1 + 2 * 64);
    } else if (tid < RPC) {
        const float* xp = x + (size_t)(r0 + tid) * TT;
        xs0[0][tid] = xp[0];
        xs0[1][tid] = xp[1];
        qx = xp[2];
    }
    float c0 = 0.f, c1 = 0.f, c2 = 0.f, c3 = 0.f;
    __syncthreads();

    for (int t = 0; t < TT; ++t) {
        float d[4][4];
        #pragma unroll
        for (int gi = 0; gi < 4; gi++) {
            d[gi][0] = bs[gi][0]; d[gi][1] = bs[gi][1];
            d[gi][2] = bs[gi][0]; d[gi][3] = bs[gi][1];
        }
        const __half* HhT = &Hh[t & 1][0][0];
        const __half* HlT = &Hl[t & 1][0][0];
        const __half* XhT = &Xh[t & 3][0][0];
        const __half* XlT = &Xl[t & 3][0][0];
        #pragma unroll
        for (int kt = 0; kt < 8; kt++) {
            if (L0 && kt >= 4) break;
            const __half *Ah, *Al; int k0;
            if (kt < 4) { Ah = HhT; Al = HlT; k0 = kt * 16; }
            else        { Ah = XhT; Al = XlT; k0 = (kt - 4) * 16; }
            unsigned a0 = *(const unsigned*)(Ah + rA * AST + k0 + cc);
            unsigned a1 = *(const unsigned*)(Ah + (rA + 8) * AST + k0 + cc);
            unsigned a2 = *(const unsigned*)(Ah + rA * AST + k0 + cc + 8);
            unsigned a3 = *(const unsigned*)(Ah + (rA + 8) * AST + k0 + cc + 8);
            unsigned e0 = *(const unsigned*)(Al + rA * AST + k0 + cc);
            unsigned e1 = *(const unsigned*)(Al + (rA + 8) * AST + k0 + cc);
            unsigned e2 = *(const unsigned*)(Al + rA * AST + k0 + cc + 8);
            unsigned e3 = *(const unsigned*)(Al + (rA + 8) * AST + k0 + cc + 8);
            #pragma unroll
            for (int gi = 0; gi < 4; gi++) {
                MMA(d[gi][0], d[gi][1], d[gi][2], d[gi][3],
                    a0, a1, a2, a3, bhi[gi][kt][0], bhi[gi][kt][1]);
                MMA(d[gi][0], d[gi][1], d[gi][2], d[gi][3],
                    e0, e1, e2, e3, bhi[gi][kt][0], bhi[gi][kt][1]);
                MMA(d[gi][0], d[gi][1], d[gi][2], d[gi][3],
                    a0, a1, a2, a3, blo[gi][kt][0], blo[gi][kt][1]);
            }
        }
        if (L0) {
            float xA = xs0[t & 3][rA], xB = xs0[t & 3][rA + 8];
            #pragma unroll
            for (int gi = 0; gi < 4; gi++) {
                d[gi][0] += ws[gi][0] * xA; d[gi][1] += ws[gi][1] * xA;
                d[gi][2] += ws[gi][0] * xB; d[gi][3] += ws[gi][1] * xB;
            }
        }
        // in-register LSTM cell update (i,f,g,o = d[0..3])
        float hv0, hv1, hv2, hv3;
        { float iv = sigf(d[0][0]), fv = sigf(d[1][0]),
                gv = tanhf_fast(d[2][0]), ov = sigf(d[3][0]);
          c0 = fv * c0 + iv * gv; hv0 = ov * tanhf_fast(c0); }
        { float iv = sigf(d[0][1]), fv = sigf(d[1][1]),
                gv = tanhf_fast(d[2][1]), ov = sigf(d[3][1]);
          c1 = fv * c1 + iv * gv; hv1 = ov * tanhf_fast(c1); }
        { float iv = sigf(d[0][2]), fv = sigf(d[1][2]),
                gv = tanhf_fast(d[2][2]), ov = sigf(d[3][2]);
          c2 = fv * c2 + iv * gv; hv2 = ov * tanhf_fast(c2); }
        { float iv = sigf(d[0][3]), fv = sigf(d[1][3]),
                gv = tanhf_fast(d[2][3]), ov = sigf(d[3][3]);
          c3 = fv * c3 + iv * gv; hv3 = ov * tanhf_fast(c3); }

        const int ns = (t + 1) & 1;
        sts_pair(&Hh[ns][rA][u0],     &Hl[ns][rA][u0],     make_float2(hv0, hv1));
        sts_pair(&Hh[ns][rA + 8][u0], &Hl[ns][rA + 8][u0], make_float2(hv2, hv3));
        *(float2*)(ho + ((size_t)(r0 + rA) * TT + t) * 64 + u0)     = make_float2(hv0, hv1);
        *(float2*)(ho + ((size_t)(r0 + rA + 8) * TT + t) * 64 + u0) = make_float2(hv2, hv3);

        if (!L0) {
            if (t + 2 < TT) {
                int sl = (t + 2) & 3;
                sts_pair(&Xh[sl][srow][su],     &Xl[sl][srow][su],     q0);
                sts_pair(&Xh[sl][srow + 8][su], &Xl[sl][srow + 8][su], q1);
            }
            if (t + 3 < TT) {
                while (ld_acquire(pf) < t + 4) __nanosleep(64);
                q0 = *(const float2*)(hp + pb0 + (size_t)(t + 3) * 64);
                q1 = *(const float2*)(hp + pb1 + (size_t)(t + 3) * 64);
            }
        } else if (tid < RPC) {
            if (t + 2 < TT) xs0[(t + 2) & 3][tid] = qx;
            if (t + 3 < TT) qx = x[(size_t)(r0 + tid) * TT + t + 3];
        }
        bool pub = (li < 4) && ((t & 1) == 1);
        if (pub) __threadfence();
        __syncthreads();
        if (pub && tid == 0) st_release(myf, t + 1);
    }
}

// ---------------------------------------------------------------------------
// Head: out = relu(relu(h) @ W1^T + b1) @ W2^T + b2.
// ---------------------------------------------------------------------------
__global__ void __launch_bounds__(256)
fc_kernel(const float* __restrict__ hin, const float* __restrict__ W1,
          const float* __restrict__ b1, const float* __restrict__ W2,
          const float* __restrict__ b2, float* __restrict__ out)
{
    __shared__ float W1T[64 * 64];
    __shared__ float b1s[64], w2s[64];
    __shared__ float hsm[8][64];
    for (int i = threadIdx.x; i < 4096; i += 256) {
        int j = i >> 6, k = i & 63;
        W1T[k * 64 + j] = W1[j * 64 + k];
    }
    if (threadIdx.x < 64) {
        b1s[threadIdx.x] = b1[threadIdx.x];
        w2s[threadIdx.x] = W2[threadIdx.x];
    }
    __syncthreads();
    const float b2v = b2[0];
    const int warp = threadIdx.x >> 5, lane = threadIdx.x & 31;
    for (int p = blockIdx.x * 8 + warp; p < BB * TT; p += gridDim.x * 8) {
        float h0 = fmaxf(hin[(size_t)p * 64 + lane], 0.f);
        float h1 = fmaxf(hin[(size_t)p * 64 + 32 + lane], 0.f);
        hsm[warp][lane] = h0; hsm[warp][lane + 32] = h1;
        __syncwarp();
        float y0 = b1s[lane], y1 = b1s[lane + 32];
        #pragma unroll
        for (int k = 0; k < 64; k++) {
            float hv = hsm[warp][k];
            y0 = fmaf(W1T[k * 64 + lane], hv, y0);
            y1 = fmaf(W1T[k * 64 + lane + 32], hv, y1);
        }
        float part = fmaxf(y0, 0.f) * w2s[lane] + fmaxf(y1, 0.f) * w2s[lane + 32];
        #pragma unroll
        for (int o = 16; o; o >>= 1) part += __shfl_down_sync(~0u, part, o);
        if (!lane) out[p] = part + b2v;
        __syncwarp();
    }
}

extern "C" void kernel_launch(void* const* d_in, const int* in_sizes, int n_in,
                              void* d_out, int out_size)
{
    const float* x    = (const float*)d_in[0];
    const float* wih0 = (const float*)d_in[1];
    const float* wihR = (const float*)d_in[2];
    const float* whh  = (const float*)d_in[3];
    const float* bih  = (const float*)d_in[4];
    const float* bhh  = (const float*)d_in[5];
    const float* W1   = (const float*)d_in[6];
    const float* b1   = (const float*)d_in[7];
    const float* W2   = (const float*)d_in[8];
    const float* b2   = (const float*)d_in[9];
    float* out = (float*)d_out;
    (void)in_sizes; (void)n_in; (void)out_size;

    void* pH = nullptr;
    cudaGetSymbolAddress(&pH, g_h);
    float* h4 = (float*)pH + 4 * (size_t)BB * TT * HH;

    reset_flags<<<1, 128>>>();
    wavefront<<<NL * CPL, 256>>>(x, wih0, wihR, whh, bih, bhh);
    fc_kernel<<<2048, 256>>>(h4, W1, b1, W2, b2, out);
}